// round 11
// baseline (speedup 1.0000x reference)
#include <cuda_runtime.h>
#include <cuda_fp16.h>
#include <cstdint>

#define NN   100000
#define NE   1000000
#define NR   8
#define NH   4
#define FIN  64
#define FOUT 64
#define DH   16
#define NBLK 98              // ceil(NN / 1024)

// ---------------- scratch (device globals; allocation-free) ----------------
__device__ __align__(16) __half g_feat[(size_t)NR * NN * FOUT];  // 102.4 MB
__device__ __align__(16) float  g_el[(size_t)NR * NN * NH];      // 12.8 MB
__device__ __align__(16) float  g_er[(size_t)NR * NN * NH];      // 12.8 MB
__device__ int   g_cnt[NN];
__device__ int   g_off[NN + 1];
__device__ int   g_wcur[NN];
__device__ int   g_bsum[NBLK];
__device__ int   g_btop[NBLK];
__device__ int   g_epk[NE];                                      // 4 MB  (pk = (r<<20)|s)

typedef unsigned long long ull;

__device__ __forceinline__ ull pack_dup(float x) {
    ull r;
    asm("mov.b64 %0, {%1, %1};" : "=l"(r) : "f"(x));
    return r;
}
__device__ __forceinline__ ull fma2(ull a, ull b, ull c) {
    ull r;
    asm("fma.rn.f32x2 %0, %1, %2, %3;" : "=l"(r) : "l"(a), "l"(b), "l"(c));
    return r;
}
__device__ __forceinline__ void unpack2(ull v, float& lo, float& hi) {
    asm("mov.b64 {%0, %1}, %2;" : "=f"(lo), "=f"(hi) : "l"(v));
}
__device__ __forceinline__ unsigned h2_to_u32(__half2 h) {
    union { __half2 h; unsigned u; } c; c.h = h; return c.u;
}
__device__ __forceinline__ __half2 u32_to_h2(unsigned u) {
    union { unsigned u; __half2 h; } c; c.u = u; return c.h;
}

// ================= CSR build =================
__global__ void k_zero() {
    int i = blockIdx.x * blockDim.x + threadIdx.x;
    if (i < NN) g_cnt[i] = 0;
}
__global__ void k_hist(const int* __restrict__ dst) {
    int e = blockIdx.x * blockDim.x + threadIdx.x;
    if (e < NE) atomicAdd(&g_cnt[dst[e]], 1);
}
__global__ void __launch_bounds__(256) k_scan_block() {
    __shared__ int ssum[256];
    int b = blockIdx.x, t = threadIdx.x;
    int base = b * 1024 + t * 4;
    int v[4], s = 0;
#pragma unroll
    for (int q = 0; q < 4; q++) {
        int idx = base + q;
        v[q] = (idx < NN) ? g_cnt[idx] : 0;
        s += v[q];
    }
    ssum[t] = s;
    __syncthreads();
#pragma unroll
    for (int off = 1; off < 256; off <<= 1) {
        int add = (t >= off) ? ssum[t - off] : 0;
        __syncthreads();
        ssum[t] += add;
        __syncthreads();
    }
    int excl = ssum[t] - s;
#pragma unroll
    for (int q = 0; q < 4; q++) {
        int idx = base + q;
        if (idx < NN) g_off[idx] = excl;
        excl += v[q];
    }
    if (t == 255) g_bsum[b] = ssum[255];
}
__global__ void __launch_bounds__(128) k_scan_tops() {
    __shared__ int sv[128];
    int t = threadIdx.x;
    int v = (t < NBLK) ? g_bsum[t] : 0;
    sv[t] = v;
    __syncthreads();
#pragma unroll
    for (int off = 1; off < 128; off <<= 1) {
        int add = (t >= off) ? sv[t - off] : 0;
        __syncthreads();
        sv[t] += add;
        __syncthreads();
    }
    if (t < NBLK) g_btop[t] = sv[t] - v;   // exclusive
    if (t == NBLK - 1) g_off[NN] = sv[t];
}
__global__ void __launch_bounds__(256) k_addoff() {
    int b = blockIdx.x, t = threadIdx.x;
    int add = g_btop[b];
    int base = b * 1024 + t * 4;
#pragma unroll
    for (int q = 0; q < 4; q++) {
        int idx = base + q;
        if (idx < NN) {
            int o = g_off[idx] + add;
            g_off[idx]  = o;
            g_wcur[idx] = o;
        }
    }
}
// scatter: pk = (r<<20)|s only
__global__ void k_scatter(const int* __restrict__ src, const int* __restrict__ dst,
                          const int* __restrict__ erel) {
    int e = blockIdx.x * blockDim.x + threadIdx.x;
    if (e >= NE) return;
    int d = dst[e];
    int pos = atomicAdd(&g_wcur[d], 1);
    g_epk[pos] = src[e] | (erel[e] << 20);
}

// ================= K1: feat = x @ W[r]  (+ fused el/er epilogue) ============
__global__ void __launch_bounds__(128) k_feat(const float* __restrict__ x,
                                              const float* __restrict__ W,
                                              const float* __restrict__ al,
                                              const float* __restrict__ ar) {
    __shared__ float xs[64][128];   // 32 KB
    __shared__ float ws[64][64];    // 16 KB
    const int r   = blockIdx.y;
    const int n0  = blockIdx.x * 128;
    const int tid = threadIdx.x;

    for (int k = tid; k < 64 * 64; k += 128) {
        int i = k >> 6, f = k & 63;
        ws[i][f] = W[(((size_t)(r * NH + (f >> 4)) * FIN + i) * DH) + (f & 15)];
    }
    {
        int gn = n0 + tid;
        const float4* x4 = (const float4*)x;
#pragma unroll
        for (int i4 = 0; i4 < 16; i4++) {
            float4 v = (gn < NN) ? x4[(size_t)gn * 16 + i4] : make_float4(0.f, 0.f, 0.f, 0.f);
            xs[i4 * 4 + 0][tid] = v.x;
            xs[i4 * 4 + 1][tid] = v.y;
            xs[i4 * 4 + 2][tid] = v.z;
            xs[i4 * 4 + 3][tid] = v.w;
        }
    }
    __syncthreads();

    const int fx = tid & 7;
    const int ny = tid >> 3;
    ull acc2[8][4];
#pragma unroll
    for (int a = 0; a < 8; a++)
#pragma unroll
        for (int p = 0; p < 4; p++) acc2[a][p] = 0ull;

#pragma unroll 4
    for (int i = 0; i < 64; i++) {
        float4 xa = *(const float4*)&xs[i][ny * 8];
        float4 xb = *(const float4*)&xs[i][ny * 8 + 4];
        ulonglong2 wlo = *(const ulonglong2*)&ws[i][fx * 8];
        ulonglong2 whi = *(const ulonglong2*)&ws[i][fx * 8 + 4];
        ull w2[4] = {wlo.x, wlo.y, whi.x, whi.y};
        float xv[8] = {xa.x, xa.y, xa.z, xa.w, xb.x, xb.y, xb.z, xb.w};
#pragma unroll
        for (int a = 0; a < 8; a++) {
            ull d = pack_dup(xv[a]);
#pragma unroll
            for (int p = 0; p < 4; p++) acc2[a][p] = fma2(d, w2[p], acc2[a][p]);
        }
    }

    float acc[8][8];
#pragma unroll
    for (int a = 0; a < 8; a++)
#pragma unroll
        for (int p = 0; p < 4; p++) unpack2(acc2[a][p], acc[a][2 * p], acc[a][2 * p + 1]);

    // store feat (fp16)
#pragma unroll
    for (int a = 0; a < 8; a++) {
        int n = n0 + ny * 8 + a;
        if (n < NN) {
            uint4 pk = make_uint4(h2_to_u32(__floats2half2_rn(acc[a][0], acc[a][1])),
                                  h2_to_u32(__floats2half2_rn(acc[a][2], acc[a][3])),
                                  h2_to_u32(__floats2half2_rn(acc[a][4], acc[a][5])),
                                  h2_to_u32(__floats2half2_rn(acc[a][6], acc[a][7])));
            *(uint4*)(g_feat + ((size_t)r * NN + n) * 64 + fx * 8) = pk;
        }
    }

    // fused el/er epilogue (fp32)
    {
        const int h  = fx >> 1;
        const int d0 = (fx & 1) * 8;
        const float* alp = al + (r * NH + h) * DH + d0;
        const float* arp = ar + (r * NH + h) * DH + d0;
        float alv[8], arv[8];
#pragma unroll
        for (int b = 0; b < 8; b++) { alv[b] = alp[b]; arv[b] = arp[b]; }
#pragma unroll
        for (int a = 0; a < 8; a++) {
            float pl = 0.f, pr = 0.f;
#pragma unroll
            for (int b = 0; b < 8; b++) { pl += acc[a][b] * alv[b]; pr += acc[a][b] * arv[b]; }
            pl += __shfl_xor_sync(0xFFFFFFFFu, pl, 1);
            pr += __shfl_xor_sync(0xFFFFFFFFu, pr, 1);
            int n = n0 + ny * 8 + a;
            if (n < NN) {
                if ((fx & 1) == 0)
                    g_el[((size_t)r * NN + n) * NH + h] = pl;
                else
                    g_er[((size_t)r * NN + n) * NH + h] = pr;
            }
        }
    }
}

// ================= K2: pull aggregation, one warp per dst, inline exp =======
// lane l owns output cols (2l, 2l+1); h = l>>3.
// er values for all (r, h) combos cached across the warp: lane l holds (r=l&7, h=l>>3).
__global__ void __launch_bounds__(256) k_agg2(float* __restrict__ out,
                                              const float* __restrict__ bias) {
    int wid_in_blk = threadIdx.x >> 5;
    int lane = threadIdx.x & 31;
    int d = blockIdx.x * 8 + wid_in_blk;
    if (d >= NN) return;
    const int h = lane >> 3;
    const int hsel = lane & 24;    // h << 3

    // cache er[(r,d,h')] at lane (h'<<3)|r
    float er_c = g_el[0]; // placeholder init (overwritten below)
    er_c = g_er[(((size_t)(lane & 7) * NN + d) << 2) + (lane >> 3)];

    int beg = g_off[d];
    int end = g_off[d + 1];

    float accx = 0.f, accy = 0.f, dn = 0.f;

    int i = beg;
    for (; i + 4 <= end; i += 4) {
        int pk0 = g_epk[i], pk1 = g_epk[i + 1], pk2 = g_epk[i + 2], pk3 = g_epk[i + 3];
        int s0 = pk0 & 0xFFFFF, r0 = pk0 >> 20;
        int s1 = pk1 & 0xFFFFF, r1 = pk1 >> 20;
        int s2 = pk2 & 0xFFFFF, r2 = pk2 >> 20;
        int s3 = pk3 & 0xFFFFF, r3 = pk3 >> 20;
        int i0 = r0 * NN + s0, i1 = r1 * NN + s1, i2 = r2 * NN + s2, i3 = r3 * NN + s3;
        float el0 = g_el[(i0 << 2) + h];
        float el1 = g_el[(i1 << 2) + h];
        float el2 = g_el[(i2 << 2) + h];
        float el3 = g_el[(i3 << 2) + h];
        unsigned f0 = *(const unsigned*)(g_feat + (size_t)i0 * 64 + 2 * lane);
        unsigned f1 = *(const unsigned*)(g_feat + (size_t)i1 * 64 + 2 * lane);
        unsigned f2 = *(const unsigned*)(g_feat + (size_t)i2 * 64 + 2 * lane);
        unsigned f3 = *(const unsigned*)(g_feat + (size_t)i3 * 64 + 2 * lane);
        float er0 = __shfl_sync(0xFFFFFFFFu, er_c, hsel | r0);
        float er1 = __shfl_sync(0xFFFFFFFFu, er_c, hsel | r1);
        float er2 = __shfl_sync(0xFFFFFFFFu, er_c, hsel | r2);
        float er3 = __shfl_sync(0xFFFFFFFFu, er_c, hsel | r3);
        float sv0 = el0 + er0, sv1 = el1 + er1, sv2 = el2 + er2, sv3 = el3 + er3;
        float ev0 = __expf(sv0 > 0.f ? sv0 : 0.2f * sv0);
        float ev1 = __expf(sv1 > 0.f ? sv1 : 0.2f * sv1);
        float ev2 = __expf(sv2 > 0.f ? sv2 : 0.2f * sv2);
        float ev3 = __expf(sv3 > 0.f ? sv3 : 0.2f * sv3);
        float2 p0 = __half22float2(u32_to_h2(f0));
        float2 p1 = __half22float2(u32_to_h2(f1));
        float2 p2 = __half22float2(u32_to_h2(f2));
        float2 p3 = __half22float2(u32_to_h2(f3));
        dn += (ev0 + ev1) + (ev2 + ev3);
        accx += p0.x * ev0 + p1.x * ev1 + p2.x * ev2 + p3.x * ev3;
        accy += p0.y * ev0 + p1.y * ev1 + p2.y * ev2 + p3.y * ev3;
    }
    for (; i < end; i++) {
        int pk0 = g_epk[i];
        int s0 = pk0 & 0xFFFFF, r0 = pk0 >> 20;
        int i0 = r0 * NN + s0;
        float el0 = g_el[(i0 << 2) + h];
        unsigned f0 = *(const unsigned*)(g_feat + (size_t)i0 * 64 + 2 * lane);
        float er0 = __shfl_sync(0xFFFFFFFFu, er_c, hsel | r0);
        float sv0 = el0 + er0;
        float ev0 = __expf(sv0 > 0.f ? sv0 : 0.2f * sv0);
        float2 p0 = __half22float2(u32_to_h2(f0));
        dn += ev0;
        accx += p0.x * ev0;
        accy += p0.y * ev0;
    }

    float w;
    asm("rcp.approx.f32 %0, %1;" : "=f"(w) : "f"(fmaxf(dn, 1e-16f)));
    float2 o;
    o.x = accx * w + bias[2 * lane];
    o.y = accy * w + bias[2 * lane + 1];
    *(float2*)(out + (size_t)d * 64 + 2 * lane) = o;
}

// ---------------- launch ----------------
extern "C" void kernel_launch(void* const* d_in, const int* in_sizes, int n_in,
                              void* d_out, int out_size) {
    const float* x    = (const float*)d_in[0];
    const int*   srci = (const int*)d_in[1];
    const int*   dsti = (const int*)d_in[2];
    const int*   erel = (const int*)d_in[3];
    const float* W    = (const float*)d_in[4];
    const float* al   = (const float*)d_in[5];
    const float* ar   = (const float*)d_in[6];
    const float* bias = (const float*)d_in[7];
    float* out = (float*)d_out;
    (void)in_sizes; (void)n_in; (void)out_size;

    k_zero<<<(NN + 255) / 256, 256>>>();
    k_hist<<<(NE + 255) / 256, 256>>>(dsti);
    k_scan_block<<<NBLK, 256>>>();
    k_scan_tops<<<1, 128>>>();
    k_addoff<<<NBLK, 256>>>();
    k_scatter<<<(NE + 255) / 256, 256>>>(srci, dsti, erel);
    {
        dim3 grid((NN + 127) / 128, NR);
        k_feat<<<grid, 128>>>(x, W, al, ar);
    }
    k_agg2<<<(NN + 7) / 8, 256>>>(out, bias);
}

// round 12
// speedup vs baseline: 1.0852x; 1.0852x over previous
#include <cuda_runtime.h>
#include <cuda_fp16.h>
#include <cstdint>

#define NN   100000
#define NE   1000000
#define NR   8
#define NH   4
#define FIN  64
#define FOUT 64
#define DH   16
#define NBLK 98              // ceil(NN / 1024)

// ---------------- scratch (device globals; allocation-free) ----------------
__device__ __align__(16) __half g_feat[(size_t)NR * NN * FOUT];  // 102.4 MB
__device__ __align__(16) float  g_el[(size_t)NR * NN * NH];      // 12.8 MB
__device__ __align__(16) float  g_er[(size_t)NR * NN * NH];      // 12.8 MB
__device__ int   g_cnt[NN];
__device__ int   g_off[NN + 1];
__device__ int   g_wcur[NN];
__device__ int   g_bsum[NBLK];
__device__ int   g_btop[NBLK];
__device__ int   g_epk[NE];                                      // 4 MB  (idx = r*NN+s)
__device__ __align__(16) float g_ecsr[(size_t)NE * NH];          // 16 MB (ev, CSR order)

__device__ __forceinline__ unsigned h2_to_u32(__half2 h) {
    union { __half2 h; unsigned u; } c; c.h = h; return c.u;
}
__device__ __forceinline__ __half2 u32_to_h2(unsigned u) {
    union { unsigned u; __half2 h; } c; c.u = u; return c.h;
}
__device__ __forceinline__ uint32_t smem_u32(const void* p) {
    uint32_t a;
    asm("{ .reg .u64 t; cvta.to.shared.u64 t, %1; cvt.u32.u64 %0, t; }" : "=r"(a) : "l"(p));
    return a;
}
#define SWZ(off) ((off) ^ (((off) >> 3) & 0x70))

#define LDM_X4(r0, r1, r2, r3, a) \
    asm volatile("ldmatrix.sync.aligned.m8n8.x4.shared.b16 {%0,%1,%2,%3}, [%4];" \
                 : "=r"(r0), "=r"(r1), "=r"(r2), "=r"(r3) : "r"(a))

#define MMA(d, a, b0, b1) \
    asm volatile("mma.sync.aligned.m16n8k16.row.col.f32.f16.f16.f32 " \
                 "{%0,%1,%2,%3},{%4,%5,%6,%7},{%8,%9},{%0,%1,%2,%3};" \
                 : "+f"((d)[0]), "+f"((d)[1]), "+f"((d)[2]), "+f"((d)[3]) \
                 : "r"((a)[0]), "r"((a)[1]), "r"((a)[2]), "r"((a)[3]), "r"(b0), "r"(b1))

// ================= CSR build =================
__global__ void k_zero() {
    int i = blockIdx.x * blockDim.x + threadIdx.x;
    if (i < NN) g_cnt[i] = 0;
}
__global__ void k_hist(const int* __restrict__ dst) {
    int e = blockIdx.x * blockDim.x + threadIdx.x;
    if (e < NE) atomicAdd(&g_cnt[dst[e]], 1);
}
__global__ void __launch_bounds__(256) k_scan_block() {
    __shared__ int ssum[256];
    int b = blockIdx.x, t = threadIdx.x;
    int base = b * 1024 + t * 4;
    int v[4], s = 0;
#pragma unroll
    for (int q = 0; q < 4; q++) {
        int idx = base + q;
        v[q] = (idx < NN) ? g_cnt[idx] : 0;
        s += v[q];
    }
    ssum[t] = s;
    __syncthreads();
#pragma unroll
    for (int off = 1; off < 256; off <<= 1) {
        int add = (t >= off) ? ssum[t - off] : 0;
        __syncthreads();
        ssum[t] += add;
        __syncthreads();
    }
    int excl = ssum[t] - s;
#pragma unroll
    for (int q = 0; q < 4; q++) {
        int idx = base + q;
        if (idx < NN) g_off[idx] = excl;
        excl += v[q];
    }
    if (t == 255) g_bsum[b] = ssum[255];
}
__global__ void __launch_bounds__(128) k_scan_tops() {
    __shared__ int sv[128];
    int t = threadIdx.x;
    int v = (t < NBLK) ? g_bsum[t] : 0;
    sv[t] = v;
    __syncthreads();
#pragma unroll
    for (int off = 1; off < 128; off <<= 1) {
        int add = (t >= off) ? sv[t - off] : 0;
        __syncthreads();
        sv[t] += add;
        __syncthreads();
    }
    if (t < NBLK) g_btop[t] = sv[t] - v;
    if (t == NBLK - 1) g_off[NN] = sv[t];
}
__global__ void __launch_bounds__(256) k_addoff() {
    int b = blockIdx.x, t = threadIdx.x;
    int add = g_btop[b];
    int base = b * 1024 + t * 4;
#pragma unroll
    for (int q = 0; q < 4; q++) {
        int idx = base + q;
        if (idx < NN) {
            int o = g_off[idx] + add;
            g_off[idx]  = o;
            g_wcur[idx] = o;
        }
    }
}
// scatter + fused exp (R10 version)
__global__ void k_scatter(const int* __restrict__ src, const int* __restrict__ dst,
                          const int* __restrict__ erel) {
    int e = blockIdx.x * blockDim.x + threadIdx.x;
    if (e >= NE) return;
    int d = dst[e], s = src[e], r = erel[e];
    int idx = r * NN + s;
    float4 el = ((const float4*)g_el)[idx];
    float4 er = ((const float4*)g_er)[(size_t)r * NN + d];
    float sv[4] = {el.x + er.x, el.y + er.y, el.z + er.z, el.w + er.w};
    float ev[4];
#pragma unroll
    for (int h = 0; h < 4; h++) {
        float lv = sv[h] > 0.f ? sv[h] : 0.2f * sv[h];
        ev[h] = __expf(lv);
    }
    int pos = atomicAdd(&g_wcur[d], 1);
    g_epk[pos] = idx;
    ((float4*)g_ecsr)[pos] = make_float4(ev[0], ev[1], ev[2], ev[3]);
}

// ================= K1: feat = x @ W[r] via mma.sync (fp16 3-term split) =====
// block: 128 threads (4 warps); 128 nodes x 64 outs x K=64; rel = blockIdx.y
__global__ void __launch_bounds__(128) k_feat_mma(const float* __restrict__ x,
                                                  const float* __restrict__ W,
                                                  const float* __restrict__ al,
                                                  const float* __restrict__ ar) {
    __shared__ __align__(16) __half s_xh[128 * 64];  // 16 KB (rows 128B, SW128)
    __shared__ __align__(16) __half s_xl[128 * 64];  // 16 KB
    __shared__ __align__(16) __half s_wh[64 * 64];   //  8 KB ([f][i] rows)
    __shared__ __align__(16) __half s_wl[64 * 64];   //  8 KB

    const int r    = blockIdx.y;
    const int n0   = blockIdx.x * 128;
    const int tid  = threadIdx.x;
    const int wid  = tid >> 5;
    const int lane = tid & 31;

    const uint32_t xh_b = smem_u32(s_xh);
    const uint32_t xl_b = smem_u32(s_xl);
    const uint32_t wh_b = smem_u32(s_wh);
    const uint32_t wl_b = smem_u32(s_wl);

    // ---- load x row (split hi/lo fp16, SW128 swizzled rows of 128B) ----
    {
        int gn = n0 + tid;
        const float4* xr = (const float4*)x + (size_t)gn * 16;
#pragma unroll
        for (int c = 0; c < 8; c++) {   // 16B chunk = 8 halves
            float4 v0, v1;
            if (gn < NN) { v0 = xr[2 * c]; v1 = xr[2 * c + 1]; }
            else { v0 = make_float4(0.f, 0.f, 0.f, 0.f); v1 = v0; }
            float f[8] = {v0.x, v0.y, v0.z, v0.w, v1.x, v1.y, v1.z, v1.w};
            unsigned ph[4], pl[4];
#pragma unroll
            for (int q = 0; q < 4; q++) {
                __half h0 = __float2half_rn(f[2 * q]);
                __half h1 = __float2half_rn(f[2 * q + 1]);
                float  l0 = f[2 * q] - __half2float(h0);
                float  l1 = f[2 * q + 1] - __half2float(h1);
                ph[q] = h2_to_u32(__halves2half2(h0, h1));
                pl[q] = h2_to_u32(__halves2half2(__float2half_rn(l0), __float2half_rn(l1)));
            }
            uint32_t off = SWZ((uint32_t)(tid * 128 + c * 16));
            *(uint4*)((char*)s_xh + off) = make_uint4(ph[0], ph[1], ph[2], ph[3]);
            *(uint4*)((char*)s_xl + off) = make_uint4(pl[0], pl[1], pl[2], pl[3]);
        }
    }
    // ---- load W as [f][i] rows (128B), split hi/lo ----
    for (int e = tid; e < 64 * 64; e += 128) {
        int f = e >> 6, i = e & 63;
        float v = W[(((size_t)(r * NH + (f >> 4)) * FIN + i) * DH) + (f & 15)];
        __half h = __float2half_rn(v);
        __half l = __float2half_rn(v - __half2float(h));
        uint32_t off = SWZ((uint32_t)(f * 128 + i * 2));
        *(__half*)((char*)s_wh + off) = h;
        *(__half*)((char*)s_wl + off) = l;
    }
    __syncthreads();

    // ---- mma mainloop ----
    const int m0 = wid * 32;
    float acc[2][8][4];
#pragma unroll
    for (int m = 0; m < 2; m++)
#pragma unroll
        for (int nt = 0; nt < 8; nt++)
#pragma unroll
            for (int q = 0; q < 4; q++) acc[m][nt][q] = 0.f;

    // ldmatrix address components
    const int a_row_in = lane & 7;
    const int a_msel   = lane >> 3;                   // 0..3
    const int b_f_in   = ((lane >> 4) << 3) + (lane & 7);
    const int b_kadd   = ((lane >> 3) & 1) * 8;

#pragma unroll
    for (int ks = 0; ks < 4; ks++) {
        const int k0 = ks * 16;
        uint32_t ah[2][4], alr[2][4];
#pragma unroll
        for (int m = 0; m < 2; m++) {
            int row = m0 + m * 16 + (a_msel & 1) * 8 + a_row_in;
            int kk  = k0 + (a_msel >> 1) * 8;
            uint32_t off = SWZ((uint32_t)(row * 128 + kk * 2));
            LDM_X4(ah[m][0],  ah[m][1],  ah[m][2],  ah[m][3],  xh_b + off);
            LDM_X4(alr[m][0], alr[m][1], alr[m][2], alr[m][3], xl_b + off);
        }
        uint32_t bh[4][4], bl[4][4];
#pragma unroll
        for (int p = 0; p < 4; p++) {   // pair p covers n-tiles 2p, 2p+1
            int f  = p * 16 + b_f_in;
            int kk = k0 + b_kadd;
            uint32_t off = SWZ((uint32_t)(f * 128 + kk * 2));
            LDM_X4(bh[p][0], bh[p][1], bh[p][2], bh[p][3], wh_b + off);
            LDM_X4(bl[p][0], bl[p][1], bl[p][2], bl[p][3], wl_b + off);
        }
#pragma unroll
        for (int m = 0; m < 2; m++)
#pragma unroll
            for (int p = 0; p < 4; p++) {
                MMA(acc[m][2 * p],     ah[m],  bh[p][0], bh[p][1]);
                MMA(acc[m][2 * p + 1], ah[m],  bh[p][2], bh[p][3]);
                MMA(acc[m][2 * p],     ah[m],  bl[p][0], bl[p][1]);
                MMA(acc[m][2 * p + 1], ah[m],  bl[p][2], bl[p][3]);
                MMA(acc[m][2 * p],     alr[m], bh[p][0], bh[p][1]);
                MMA(acc[m][2 * p + 1], alr[m], bh[p][2], bh[p][3]);
            }
    }
    __syncthreads();   // done reading s_xh/s_xl — reuse s_xh for feat staging

    // ---- stage feat (fp16) into s_xh, swizzled; compute el/er partials ----
    const int q4 = lane >> 2;       // 0..7 (row within 8)
    const int c4 = lane & 3;        // col pair
#pragma unroll
    for (int m = 0; m < 2; m++)
#pragma unroll
        for (int rh = 0; rh < 2; rh++) {
            int rowg = m0 + m * 16 + rh * 8 + q4;   // local row 0..127
            // stage this row's 16 cols as 8 half2
#pragma unroll
            for (int nt = 0; nt < 8; nt++) {
                __half2 hv = __floats2half2_rn(acc[m][nt][rh * 2], acc[m][nt][rh * 2 + 1]);
                uint32_t off = SWZ((uint32_t)(rowg * 128 + (nt * 8 + c4 * 2) * 2));
                *(unsigned*)((char*)s_xh + off) = h2_to_u32(hv);
            }
            // el/er partials over this thread's 16 cols
            float el4[4] = {0.f, 0.f, 0.f, 0.f}, er4[4] = {0.f, 0.f, 0.f, 0.f};
#pragma unroll
            for (int nt = 0; nt < 8; nt++) {
                int col = nt * 8 + c4 * 2;
                int h = nt >> 1;
                float v0 = acc[m][nt][rh * 2], v1 = acc[m][nt][rh * 2 + 1];
                el4[h] += v0 * al[r * 64 + col] + v1 * al[r * 64 + col + 1];
                er4[h] += v0 * ar[r * 64 + col] + v1 * ar[r * 64 + col + 1];
            }
#pragma unroll
            for (int h = 0; h < 4; h++) {
                el4[h] += __shfl_xor_sync(0xFFFFFFFFu, el4[h], 1);
                el4[h] += __shfl_xor_sync(0xFFFFFFFFu, el4[h], 2);
                er4[h] += __shfl_xor_sync(0xFFFFFFFFu, er4[h], 1);
                er4[h] += __shfl_xor_sync(0xFFFFFFFFu, er4[h], 2);
            }
            int n = n0 + rowg;
            if (n < NN) {
                if (c4 == 0)
                    ((float4*)g_el)[(size_t)r * NN + n] = make_float4(el4[0], el4[1], el4[2], el4[3]);
                else if (c4 == 1)
                    ((float4*)g_er)[(size_t)r * NN + n] = make_float4(er4[0], er4[1], er4[2], er4[3]);
            }
        }
    __syncthreads();

    // ---- coalesced feat store: thread owns row tid ----
    {
        int n = n0 + tid;
        if (n < NN) {
            uint4* dst = (uint4*)(g_feat + ((size_t)r * NN + n) * 64);
#pragma unroll
            for (int c = 0; c < 8; c++) {
                uint32_t off = SWZ((uint32_t)(tid * 128 + c * 16));
                dst[c] = *(const uint4*)((const char*)s_xh + off);
            }
        }
    }
}

// ================= K2: pull aggregation (R10 version) =======================
__global__ void __launch_bounds__(256) k_agg2(float* __restrict__ out,
                                              const float* __restrict__ bias) {
    int wid_in_blk = threadIdx.x >> 5;
    int lane = threadIdx.x & 31;
    int d = blockIdx.x * 8 + wid_in_blk;
    if (d >= NN) return;
    const int h = lane >> 3;

    int beg = g_off[d];
    int end = g_off[d + 1];

    float accx = 0.f, accy = 0.f, dn = 0.f;

    int i = beg;
    for (; i + 2 <= end; i += 2) {
        int idx0 = g_epk[i];
        int idx1 = g_epk[i + 1];
        float ev0 = g_ecsr[(size_t)(i) * 4 + h];
        float ev1 = g_ecsr[(size_t)(i + 1) * 4 + h];
        unsigned f0 = *(const unsigned*)(g_feat + (size_t)idx0 * 64 + 2 * lane);
        unsigned f1 = *(const unsigned*)(g_feat + (size_t)idx1 * 64 + 2 * lane);
        float2 p0 = __half22float2(u32_to_h2(f0));
        float2 p1 = __half22float2(u32_to_h2(f1));
        dn += ev0 + ev1;
        accx += p0.x * ev0 + p1.x * ev1;
        accy += p0.y * ev0 + p1.y * ev1;
    }
    if (i < end) {
        int idx0 = g_epk[i];
        float ev0 = g_ecsr[(size_t)i * 4 + h];
        unsigned f0 = *(const unsigned*)(g_feat + (size_t)idx0 * 64 + 2 * lane);
        float2 p0 = __half22float2(u32_to_h2(f0));
        dn += ev0;
        accx += p0.x * ev0;
        accy += p0.y * ev0;
    }

    float w;
    asm("rcp.approx.f32 %0, %1;" : "=f"(w) : "f"(fmaxf(dn, 1e-16f)));
    float2 o;
    o.x = accx * w + bias[2 * lane];
    o.y = accy * w + bias[2 * lane + 1];
    *(float2*)(out + (size_t)d * 64 + 2 * lane) = o;
}

// ---------------- launch ----------------
extern "C" void kernel_launch(void* const* d_in, const int* in_sizes, int n_in,
                              void* d_out, int out_size) {
    const float* x    = (const float*)d_in[0];
    const int*   srci = (const int*)d_in[1];
    const int*   dsti = (const int*)d_in[2];
    const int*   erel = (const int*)d_in[3];
    const float* W    = (const float*)d_in[4];
    const float* al   = (const float*)d_in[5];
    const float* ar   = (const float*)d_in[6];
    const float* bias = (const float*)d_in[7];
    float* out = (float*)d_out;
    (void)in_sizes; (void)n_in; (void)out_size;

    k_zero<<<(NN + 255) / 256, 256>>>();
    k_hist<<<(NE + 255) / 256, 256>>>(dsti);
    k_scan_block<<<NBLK, 256>>>();
    k_scan_tops<<<1, 128>>>();
    k_addoff<<<NBLK, 256>>>();
    {
        dim3 grid((NN + 127) / 128, NR);
        k_feat_mma<<<grid, 128>>>(x, W, al, ar);
    }
    k_scatter<<<(NE + 255) / 256, 256>>>(srci, dsti, erel);
    k_agg2<<<(NN + 7) / 8, 256>>>(out, bias);
}

// round 13
// speedup vs baseline: 1.1306x; 1.0418x over previous
#include <cuda_runtime.h>
#include <cuda_fp16.h>
#include <cstdint>

#define NN   100000
#define NE   1000000
#define NR   8
#define NH   4
#define FIN  64
#define FOUT 64
#define DH   16
#define NBLK 98              // ceil(NN / 1024)

// ---------------- scratch (device globals; allocation-free) ----------------
__device__ __align__(16) __half g_feat[(size_t)NR * NN * FOUT];  // 102.4 MB
__device__ __align__(16) float  g_el[(size_t)NR * NN * NH];      // 12.8 MB
__device__ __align__(16) float  g_er[(size_t)NR * NN * NH];      // 12.8 MB
__device__ int   g_cnt[NN];
__device__ int   g_off[NN + 1];
__device__ int   g_wcur[NN];
__device__ int   g_bsum[NBLK];
__device__ int   g_btop[NBLK];
__device__ int   g_epk[NE];                                      // 4 MB  (idx = r*NN+s)
__device__ __align__(16) float g_ecsr[(size_t)NE * NH];          // 16 MB (ev, CSR order)

__device__ __forceinline__ unsigned h2_to_u32(__half2 h) {
    union { __half2 h; unsigned u; } c; c.h = h; return c.u;
}
__device__ __forceinline__ __half2 u32_to_h2(unsigned u) {
    union { unsigned u; __half2 h; } c; c.u = u; return c.h;
}
__device__ __forceinline__ uint32_t smem_u32(const void* p) {
    uint32_t a;
    asm("{ .reg .u64 t; cvta.to.shared.u64 t, %1; cvt.u32.u64 %0, t; }" : "=r"(a) : "l"(p));
    return a;
}
#define SWZ(off) ((off) ^ (((off) >> 3) & 0x70))

#define LDM_X4(r0, r1, r2, r3, a) \
    asm volatile("ldmatrix.sync.aligned.m8n8.x4.shared.b16 {%0,%1,%2,%3}, [%4];" \
                 : "=r"(r0), "=r"(r1), "=r"(r2), "=r"(r3) : "r"(a))

#define MMA(d, a, b0, b1) \
    asm volatile("mma.sync.aligned.m16n8k16.row.col.f32.f16.f16.f32 " \
                 "{%0,%1,%2,%3},{%4,%5,%6,%7},{%8,%9},{%0,%1,%2,%3};" \
                 : "+f"((d)[0]), "+f"((d)[1]), "+f"((d)[2]), "+f"((d)[3]) \
                 : "r"((a)[0]), "r"((a)[1]), "r"((a)[2]), "r"((a)[3]), "r"(b0), "r"(b1))

// ================= CSR build =================
__global__ void k_zero() {
    int i = blockIdx.x * blockDim.x + threadIdx.x;
    if (i < NN) g_cnt[i] = 0;
}
__global__ void k_hist(const int* __restrict__ dst) {
    int e = blockIdx.x * blockDim.x + threadIdx.x;
    if (e < NE) atomicAdd(&g_cnt[dst[e]], 1);
}
__global__ void __launch_bounds__(256) k_scan_block() {
    __shared__ int ssum[256];
    int b = blockIdx.x, t = threadIdx.x;
    int base = b * 1024 + t * 4;
    int v[4], s = 0;
#pragma unroll
    for (int q = 0; q < 4; q++) {
        int idx = base + q;
        v[q] = (idx < NN) ? g_cnt[idx] : 0;
        s += v[q];
    }
    ssum[t] = s;
    __syncthreads();
#pragma unroll
    for (int off = 1; off < 256; off <<= 1) {
        int add = (t >= off) ? ssum[t - off] : 0;
        __syncthreads();
        ssum[t] += add;
        __syncthreads();
    }
    int excl = ssum[t] - s;
#pragma unroll
    for (int q = 0; q < 4; q++) {
        int idx = base + q;
        if (idx < NN) g_off[idx] = excl;
        excl += v[q];
    }
    if (t == 255) g_bsum[b] = ssum[255];
}
__global__ void __launch_bounds__(128) k_scan_tops() {
    __shared__ int sv[128];
    int t = threadIdx.x;
    int v = (t < NBLK) ? g_bsum[t] : 0;
    sv[t] = v;
    __syncthreads();
#pragma unroll
    for (int off = 1; off < 128; off <<= 1) {
        int add = (t >= off) ? sv[t - off] : 0;
        __syncthreads();
        sv[t] += add;
        __syncthreads();
    }
    if (t < NBLK) g_btop[t] = sv[t] - v;
    if (t == NBLK - 1) g_off[NN] = sv[t];
}
__global__ void __launch_bounds__(256) k_addoff() {
    int b = blockIdx.x, t = threadIdx.x;
    int add = g_btop[b];
    int base = b * 1024 + t * 4;
#pragma unroll
    for (int q = 0; q < 4; q++) {
        int idx = base + q;
        if (idx < NN) {
            int o = g_off[idx] + add;
            g_off[idx]  = o;
            g_wcur[idx] = o;
        }
    }
}
// scatter + fused exp
__global__ void k_scatter(const int* __restrict__ src, const int* __restrict__ dst,
                          const int* __restrict__ erel) {
    int e = blockIdx.x * blockDim.x + threadIdx.x;
    if (e >= NE) return;
    int d = dst[e], s = src[e], r = erel[e];
    int idx = r * NN + s;
    float4 el = ((const float4*)g_el)[idx];
    float4 er = ((const float4*)g_er)[(size_t)r * NN + d];
    float sv[4] = {el.x + er.x, el.y + er.y, el.z + er.z, el.w + er.w};
    float ev[4];
#pragma unroll
    for (int h = 0; h < 4; h++) {
        float lv = sv[h] > 0.f ? sv[h] : 0.2f * sv[h];
        ev[h] = __expf(lv);
    }
    int pos = atomicAdd(&g_wcur[d], 1);
    g_epk[pos] = idx;
    ((float4*)g_ecsr)[pos] = make_float4(ev[0], ev[1], ev[2], ev[3]);
}

// ================= K1: feat = x @ W[r] via mma.sync, all rels per block =====
// grid = ceil(NN/128); loop over 8 relations with x tile resident in smem
__global__ void __launch_bounds__(128) k_feat_mma(const float* __restrict__ x,
                                                  const float* __restrict__ W,
                                                  const float* __restrict__ al,
                                                  const float* __restrict__ ar) {
    __shared__ __align__(16) __half s_xh[128 * 64];  // 16 KB
    __shared__ __align__(16) __half s_xl[128 * 64];  // 16 KB
    __shared__ __align__(16) __half s_wh[64 * 64];   //  8 KB
    __shared__ __align__(16) __half s_wl[64 * 64];   //  8 KB
    __shared__ __align__(16) __half s_st[128 * 64];  // 16 KB staging

    const int n0   = blockIdx.x * 128;
    const int tid  = threadIdx.x;
    const int wid  = tid >> 5;
    const int lane = tid & 31;

    const uint32_t xh_b = smem_u32(s_xh);
    const uint32_t xl_b = smem_u32(s_xl);
    const uint32_t wh_b = smem_u32(s_wh);
    const uint32_t wl_b = smem_u32(s_wl);

    // ---- load x row ONCE (split hi/lo fp16, SW128 swizzled rows of 128B) ----
    {
        int gn = n0 + tid;
        const float4* xr = (const float4*)x + (size_t)gn * 16;
#pragma unroll
        for (int c = 0; c < 8; c++) {
            float4 v0, v1;
            if (gn < NN) { v0 = xr[2 * c]; v1 = xr[2 * c + 1]; }
            else { v0 = make_float4(0.f, 0.f, 0.f, 0.f); v1 = v0; }
            float f[8] = {v0.x, v0.y, v0.z, v0.w, v1.x, v1.y, v1.z, v1.w};
            unsigned ph[4], pl[4];
#pragma unroll
            for (int q = 0; q < 4; q++) {
                __half h0 = __float2half_rn(f[2 * q]);
                __half h1 = __float2half_rn(f[2 * q + 1]);
                float  l0 = f[2 * q] - __half2float(h0);
                float  l1 = f[2 * q + 1] - __half2float(h1);
                ph[q] = h2_to_u32(__halves2half2(h0, h1));
                pl[q] = h2_to_u32(__halves2half2(__float2half_rn(l0), __float2half_rn(l1)));
            }
            uint32_t off = SWZ((uint32_t)(tid * 128 + c * 16));
            *(uint4*)((char*)s_xh + off) = make_uint4(ph[0], ph[1], ph[2], ph[3]);
            *(uint4*)((char*)s_xl + off) = make_uint4(pl[0], pl[1], pl[2], pl[3]);
        }
    }

    // ldmatrix address components (loop-invariant)
    const int m0       = wid * 32;
    const int a_row_in = lane & 7;
    const int a_msel   = lane >> 3;
    const int b_f_in   = ((lane >> 4) << 3) + (lane & 7);
    const int b_kadd   = ((lane >> 3) & 1) * 8;
    const int q4 = lane >> 2;
    const int c4 = lane & 3;

    for (int r = 0; r < NR; r++) {
        __syncthreads();   // protects W overwrite + s_st reuse + (r==0) x tile ready

        // ---- load W[r] as [f][i] rows (128B), split hi/lo ----
        for (int e = tid; e < 64 * 64; e += 128) {
            int f = e >> 6, i = e & 63;
            float v = W[(((size_t)(r * NH + (f >> 4)) * FIN + i) * DH) + (f & 15)];
            __half h = __float2half_rn(v);
            __half l = __float2half_rn(v - __half2float(h));
            uint32_t off = SWZ((uint32_t)(f * 128 + i * 2));
            *(__half*)((char*)s_wh + off) = h;
            *(__half*)((char*)s_wl + off) = l;
        }
        __syncthreads();

        // ---- mma mainloop ----
        float acc[2][8][4];
#pragma unroll
        for (int m = 0; m < 2; m++)
#pragma unroll
            for (int nt = 0; nt < 8; nt++)
#pragma unroll
                for (int q = 0; q < 4; q++) acc[m][nt][q] = 0.f;

#pragma unroll
        for (int ks = 0; ks < 4; ks++) {
            const int k0 = ks * 16;
            uint32_t ah[2][4], alr[2][4];
#pragma unroll
            for (int m = 0; m < 2; m++) {
                int row = m0 + m * 16 + (a_msel & 1) * 8 + a_row_in;
                int kk  = k0 + (a_msel >> 1) * 8;
                uint32_t off = SWZ((uint32_t)(row * 128 + kk * 2));
                LDM_X4(ah[m][0],  ah[m][1],  ah[m][2],  ah[m][3],  xh_b + off);
                LDM_X4(alr[m][0], alr[m][1], alr[m][2], alr[m][3], xl_b + off);
            }
            uint32_t bh[4][4], bl[4][4];
#pragma unroll
            for (int p = 0; p < 4; p++) {
                int f  = p * 16 + b_f_in;
                int kk = k0 + b_kadd;
                uint32_t off = SWZ((uint32_t)(f * 128 + kk * 2));
                LDM_X4(bh[p][0], bh[p][1], bh[p][2], bh[p][3], wh_b + off);
                LDM_X4(bl[p][0], bl[p][1], bl[p][2], bl[p][3], wl_b + off);
            }
#pragma unroll
            for (int m = 0; m < 2; m++)
#pragma unroll
                for (int p = 0; p < 4; p++) {
                    MMA(acc[m][2 * p],     ah[m],  bh[p][0], bh[p][1]);
                    MMA(acc[m][2 * p + 1], ah[m],  bh[p][2], bh[p][3]);
                    MMA(acc[m][2 * p],     ah[m],  bl[p][0], bl[p][1]);
                    MMA(acc[m][2 * p + 1], ah[m],  bl[p][2], bl[p][3]);
                    MMA(acc[m][2 * p],     alr[m], bh[p][0], bh[p][1]);
                    MMA(acc[m][2 * p + 1], alr[m], bh[p][2], bh[p][3]);
                }
        }

        // ---- stage feat (fp16) into s_st; compute el/er ----
#pragma unroll
        for (int m = 0; m < 2; m++)
#pragma unroll
            for (int rh = 0; rh < 2; rh++) {
                int rowg = m0 + m * 16 + rh * 8 + q4;
#pragma unroll
                for (int nt = 0; nt < 8; nt++) {
                    __half2 hv = __floats2half2_rn(acc[m][nt][rh * 2], acc[m][nt][rh * 2 + 1]);
                    uint32_t off = SWZ((uint32_t)(rowg * 128 + (nt * 8 + c4 * 2) * 2));
                    *(unsigned*)((char*)s_st + off) = h2_to_u32(hv);
                }
                float el4[4] = {0.f, 0.f, 0.f, 0.f}, er4[4] = {0.f, 0.f, 0.f, 0.f};
#pragma unroll
                for (int nt = 0; nt < 8; nt++) {
                    int col = nt * 8 + c4 * 2;
                    int h = nt >> 1;
                    float v0 = acc[m][nt][rh * 2], v1 = acc[m][nt][rh * 2 + 1];
                    el4[h] += v0 * al[r * 64 + col] + v1 * al[r * 64 + col + 1];
                    er4[h] += v0 * ar[r * 64 + col] + v1 * ar[r * 64 + col + 1];
                }
#pragma unroll
                for (int h = 0; h < 4; h++) {
                    el4[h] += __shfl_xor_sync(0xFFFFFFFFu, el4[h], 1);
                    el4[h] += __shfl_xor_sync(0xFFFFFFFFu, el4[h], 2);
                    er4[h] += __shfl_xor_sync(0xFFFFFFFFu, er4[h], 1);
                    er4[h] += __shfl_xor_sync(0xFFFFFFFFu, er4[h], 2);
                }
                int n = n0 + rowg;
                if (n < NN) {
                    if (c4 == 0)
                        ((float4*)g_el)[(size_t)r * NN + n] = make_float4(el4[0], el4[1], el4[2], el4[3]);
                    else if (c4 == 1)
                        ((float4*)g_er)[(size_t)r * NN + n] = make_float4(er4[0], er4[1], er4[2], er4[3]);
                }
            }
        __syncthreads();

        // ---- coalesced feat store: thread owns row tid ----
        {
            int n = n0 + tid;
            if (n < NN) {
                uint4* dst = (uint4*)(g_feat + ((size_t)r * NN + n) * 64);
#pragma unroll
                for (int c = 0; c < 8; c++) {
                    uint32_t off = SWZ((uint32_t)(tid * 128 + c * 16));
                    dst[c] = *(const uint4*)((const char*)s_st + off);
                }
            }
        }
    }
}

// ================= K2: pull aggregation (unroll x4) =========================
__global__ void __launch_bounds__(256) k_agg2(float* __restrict__ out,
                                              const float* __restrict__ bias) {
    int wid_in_blk = threadIdx.x >> 5;
    int lane = threadIdx.x & 31;
    int d = blockIdx.x * 8 + wid_in_blk;
    if (d >= NN) return;
    const int h = lane >> 3;

    int beg = g_off[d];
    int end = g_off[d + 1];

    float accx = 0.f, accy = 0.f, dn = 0.f;

    int i = beg;
    for (; i + 4 <= end; i += 4) {
        int idx0 = g_epk[i], idx1 = g_epk[i + 1], idx2 = g_epk[i + 2], idx3 = g_epk[i + 3];
        float ev0 = g_ecsr[(size_t)(i) * 4 + h];
        float ev1 = g_ecsr[(size_t)(i + 1) * 4 + h];
        float ev2 = g_ecsr[(size_t)(i + 2) * 4 + h];
        float ev3 = g_ecsr[(size_t)(i + 3) * 4 + h];
        unsigned f0 = *(const unsigned*)(g_feat + (size_t)idx0 * 64 + 2 * lane);
        unsigned f1 = *(const unsigned*)(g_feat + (size_t)idx1 * 64 + 2 * lane);
        unsigned f2 = *(const unsigned*)(g_feat + (size_t)idx2 * 64 + 2 * lane);
        unsigned f3 = *(const unsigned*)(g_feat + (size_t)idx3 * 64 + 2 * lane);
        float2 p0 = __half22float2(u32_to_h2(f0));
        float2 p1 = __half22float2(u32_to_h2(f1));
        float2 p2 = __half22float2(u32_to_h2(f2));
        float2 p3 = __half22float2(u32_to_h2(f3));
        dn += (ev0 + ev1) + (ev2 + ev3);
        accx += p0.x * ev0 + p1.x * ev1 + p2.x * ev2 + p3.x * ev3;
        accy += p0.y * ev0 + p1.y * ev1 + p2.y * ev2 + p3.y * ev3;
    }
    for (; i < end; i++) {
        int idx0 = g_epk[i];
        float ev0 = g_ecsr[(size_t)i * 4 + h];
        unsigned f0 = *(const unsigned*)(g_feat + (size_t)idx0 * 64 + 2 * lane);
        float2 p0 = __half22float2(u32_to_h2(f0));
        dn += ev0;
        accx += p0.x * ev0;
        accy += p0.y * ev0;
    }

    float w;
    asm("rcp.approx.f32 %0, %1;" : "=f"(w) : "f"(fmaxf(dn, 1e-16f)));
    float2 o;
    o.x = accx * w + bias[2 * lane];
    o.y = accy * w + bias[2 * lane + 1];
    *(float2*)(out + (size_t)d * 64 + 2 * lane) = o;
}

// ---------------- launch ----------------
extern "C" void kernel_launch(void* const* d_in, const int* in_sizes, int n_in,
                              void* d_out, int out_size) {
    const float* x    = (const float*)d_in[0];
    const int*   srci = (const int*)d_in[1];
    const int*   dsti = (const int*)d_in[2];
    const int*   erel = (const int*)d_in[3];
    const float* W    = (const float*)d_in[4];
    const float* al   = (const float*)d_in[5];
    const float* ar   = (const float*)d_in[6];
    const float* bias = (const float*)d_in[7];
    float* out = (float*)d_out;
    (void)in_sizes; (void)n_in; (void)out_size;

    k_zero<<<(NN + 255) / 256, 256>>>();
    k_hist<<<(NE + 255) / 256, 256>>>(dsti);
    k_scan_block<<<NBLK, 256>>>();
    k_scan_tops<<<1, 128>>>();
    k_addoff<<<NBLK, 256>>>();
    k_feat_mma<<<(NN + 127) / 128, 128>>>(x, W, al, ar);
    k_scatter<<<(NE + 255) / 256, 256>>>(srci, dsti, erel);
    k_agg2<<<(NN + 7) / 8, 256>>>(out, bias);
}

// round 14
// speedup vs baseline: 1.1738x; 1.0382x over previous
#include <cuda_runtime.h>
#include <cuda_fp16.h>
#include <cstdint>

#define NN   100000
#define NE   1000000
#define NR   8
#define NH   4
#define FIN  64
#define FOUT 64
#define DH   16
#define NBLK 98              // ceil(NN / 1024)

#define FEAT_BLOCKS 782      // ceil(NN/128)
#define HIST_BLOCKS 391      // every 3rd block of the fused grid
#define FUSED_GRID  (FEAT_BLOCKS + HIST_BLOCKS)   // 1173
#define HIST_EPB    2560     // edges per hist block (391*2560 >= 1e6)

// ---------------- scratch (device globals; allocation-free) ----------------
__device__ __align__(16) __half g_feat[(size_t)NR * NN * FOUT];  // 102.4 MB
__device__ __align__(16) float  g_el[(size_t)NR * NN * NH];      // 12.8 MB
__device__ __align__(16) float  g_er[(size_t)NR * NN * NH];      // 12.8 MB
__device__ int   g_cnt[NN];          // zero at entry (static init + agg2 restore)
__device__ int   g_off[NN + 1];
__device__ int   g_wcur[NN];
__device__ int   g_bsum[NBLK];
__device__ int   g_epk[NE];                                      // 4 MB  (idx = r*NN+s)
__device__ __align__(16) __half g_ecsr[(size_t)NE * NH];         // 8 MB (ev fp16, CSR order)

__device__ __forceinline__ unsigned h2_to_u32(__half2 h) {
    union { __half2 h; unsigned u; } c; c.h = h; return c.u;
}
__device__ __forceinline__ __half2 u32_to_h2(unsigned u) {
    union { unsigned u; __half2 h; } c; c.u = u; return c.h;
}
__device__ __forceinline__ uint32_t smem_u32(const void* p) {
    uint32_t a;
    asm("{ .reg .u64 t; cvta.to.shared.u64 t, %1; cvt.u32.u64 %0, t; }" : "=r"(a) : "l"(p));
    return a;
}
#define SWZ(off) ((off) ^ (((off) >> 3) & 0x70))

#define LDM_X4(r0, r1, r2, r3, a) \
    asm volatile("ldmatrix.sync.aligned.m8n8.x4.shared.b16 {%0,%1,%2,%3}, [%4];" \
                 : "=r"(r0), "=r"(r1), "=r"(r2), "=r"(r3) : "r"(a))

#define MMA(d, a, b0, b1) \
    asm volatile("mma.sync.aligned.m16n8k16.row.col.f32.f16.f16.f32 " \
                 "{%0,%1,%2,%3},{%4,%5,%6,%7},{%8,%9},{%0,%1,%2,%3};" \
                 : "+f"((d)[0]), "+f"((d)[1]), "+f"((d)[2]), "+f"((d)[3]) \
                 : "r"((a)[0]), "r"((a)[1]), "r"((a)[2]), "r"((a)[3]), "r"(b0), "r"(b1))

// ================= K1: fused feat-GEMM (mma.sync) + dst histogram ===========
// grid = FUSED_GRID; bid%3==2 -> histogram block, else feat block.
__global__ void __launch_bounds__(128) k_feat_hist(const float* __restrict__ x,
                                                   const float* __restrict__ W,
                                                   const float* __restrict__ al,
                                                   const float* __restrict__ ar,
                                                   const int* __restrict__ dst) {
    __shared__ __align__(16) __half s_xh[128 * 64];  // 16 KB
    __shared__ __align__(16) __half s_xl[128 * 64];  // 16 KB
    __shared__ __align__(16) __half s_wh[64 * 64];   //  8 KB
    __shared__ __align__(16) __half s_wl[64 * 64];   //  8 KB
    __shared__ __align__(16) __half s_st[128 * 64];  // 16 KB staging

    const int bid = blockIdx.x;
    const int tid = threadIdx.x;

    if (bid % 3 == 2) {
        // ---- histogram role ----
        int hb = bid / 3;
        int e0 = hb * HIST_EPB + tid;
        int eEnd = min((hb + 1) * HIST_EPB, NE);
#pragma unroll 4
        for (int e = e0; e < eEnd; e += 128)
            atomicAdd(&g_cnt[dst[e]], 1);
        return;
    }
    const int fb = bid - bid / 3;        // 0..FEAT_BLOCKS-1
    const int n0 = fb * 128;
    const int wid  = tid >> 5;
    const int lane = tid & 31;

    const uint32_t xh_b = smem_u32(s_xh);
    const uint32_t xl_b = smem_u32(s_xl);
    const uint32_t wh_b = smem_u32(s_wh);
    const uint32_t wl_b = smem_u32(s_wl);

    // ---- load x row ONCE (split hi/lo fp16, SW128 swizzled rows of 128B) ----
    {
        int gn = n0 + tid;
        const float4* xr = (const float4*)x + (size_t)gn * 16;
#pragma unroll
        for (int c = 0; c < 8; c++) {
            float4 v0, v1;
            if (gn < NN) { v0 = xr[2 * c]; v1 = xr[2 * c + 1]; }
            else { v0 = make_float4(0.f, 0.f, 0.f, 0.f); v1 = v0; }
            float f[8] = {v0.x, v0.y, v0.z, v0.w, v1.x, v1.y, v1.z, v1.w};
            unsigned ph[4], pl[4];
#pragma unroll
            for (int q = 0; q < 4; q++) {
                __half h0 = __float2half_rn(f[2 * q]);
                __half h1 = __float2half_rn(f[2 * q + 1]);
                float  l0 = f[2 * q] - __half2float(h0);
                float  l1 = f[2 * q + 1] - __half2float(h1);
                ph[q] = h2_to_u32(__halves2half2(h0, h1));
                pl[q] = h2_to_u32(__halves2half2(__float2half_rn(l0), __float2half_rn(l1)));
            }
            uint32_t off = SWZ((uint32_t)(tid * 128 + c * 16));
            *(uint4*)((char*)s_xh + off) = make_uint4(ph[0], ph[1], ph[2], ph[3]);
            *(uint4*)((char*)s_xl + off) = make_uint4(pl[0], pl[1], pl[2], pl[3]);
        }
    }

    const int m0       = wid * 32;
    const int a_row_in = lane & 7;
    const int a_msel   = lane >> 3;
    const int b_f_in   = ((lane >> 4) << 3) + (lane & 7);
    const int b_kadd   = ((lane >> 3) & 1) * 8;
    const int q4 = lane >> 2;
    const int c4 = lane & 3;

    for (int r = 0; r < NR; r++) {
        __syncthreads();

        // ---- load W[r] as [f][i] rows (128B), split hi/lo ----
        for (int e = tid; e < 64 * 64; e += 128) {
            int f = e >> 6, i = e & 63;
            float v = W[(((size_t)(r * NH + (f >> 4)) * FIN + i) * DH) + (f & 15)];
            __half h = __float2half_rn(v);
            __half l = __float2half_rn(v - __half2float(h));
            uint32_t off = SWZ((uint32_t)(f * 128 + i * 2));
            *(__half*)((char*)s_wh + off) = h;
            *(__half*)((char*)s_wl + off) = l;
        }
        __syncthreads();

        float acc[2][8][4];
#pragma unroll
        for (int m = 0; m < 2; m++)
#pragma unroll
            for (int nt = 0; nt < 8; nt++)
#pragma unroll
                for (int q = 0; q < 4; q++) acc[m][nt][q] = 0.f;

#pragma unroll
        for (int ks = 0; ks < 4; ks++) {
            const int k0 = ks * 16;
            uint32_t ah[2][4], alr[2][4];
#pragma unroll
            for (int m = 0; m < 2; m++) {
                int row = m0 + m * 16 + (a_msel & 1) * 8 + a_row_in;
                int kk  = k0 + (a_msel >> 1) * 8;
                uint32_t off = SWZ((uint32_t)(row * 128 + kk * 2));
                LDM_X4(ah[m][0],  ah[m][1],  ah[m][2],  ah[m][3],  xh_b + off);
                LDM_X4(alr[m][0], alr[m][1], alr[m][2], alr[m][3], xl_b + off);
            }
            uint32_t bh[4][4], bl[4][4];
#pragma unroll
            for (int p = 0; p < 4; p++) {
                int f  = p * 16 + b_f_in;
                int kk = k0 + b_kadd;
                uint32_t off = SWZ((uint32_t)(f * 128 + kk * 2));
                LDM_X4(bh[p][0], bh[p][1], bh[p][2], bh[p][3], wh_b + off);
                LDM_X4(bl[p][0], bl[p][1], bl[p][2], bl[p][3], wl_b + off);
            }
#pragma unroll
            for (int m = 0; m < 2; m++)
#pragma unroll
                for (int p = 0; p < 4; p++) {
                    MMA(acc[m][2 * p],     ah[m],  bh[p][0], bh[p][1]);
                    MMA(acc[m][2 * p + 1], ah[m],  bh[p][2], bh[p][3]);
                    MMA(acc[m][2 * p],     ah[m],  bl[p][0], bl[p][1]);
                    MMA(acc[m][2 * p + 1], ah[m],  bl[p][2], bl[p][3]);
                    MMA(acc[m][2 * p],     alr[m], bh[p][0], bh[p][1]);
                    MMA(acc[m][2 * p + 1], alr[m], bh[p][2], bh[p][3]);
                }
        }

        // ---- stage feat (fp16) into s_st; compute el/er ----
#pragma unroll
        for (int m = 0; m < 2; m++)
#pragma unroll
            for (int rh = 0; rh < 2; rh++) {
                int rowg = m0 + m * 16 + rh * 8 + q4;
#pragma unroll
                for (int nt = 0; nt < 8; nt++) {
                    __half2 hv = __floats2half2_rn(acc[m][nt][rh * 2], acc[m][nt][rh * 2 + 1]);
                    uint32_t off = SWZ((uint32_t)(rowg * 128 + (nt * 8 + c4 * 2) * 2));
                    *(unsigned*)((char*)s_st + off) = h2_to_u32(hv);
                }
                float el4[4] = {0.f, 0.f, 0.f, 0.f}, er4[4] = {0.f, 0.f, 0.f, 0.f};
#pragma unroll
                for (int nt = 0; nt < 8; nt++) {
                    int col = nt * 8 + c4 * 2;
                    int h = nt >> 1;
                    float v0 = acc[m][nt][rh * 2], v1 = acc[m][nt][rh * 2 + 1];
                    el4[h] += v0 * al[r * 64 + col] + v1 * al[r * 64 + col + 1];
                    er4[h] += v0 * ar[r * 64 + col] + v1 * ar[r * 64 + col + 1];
                }
#pragma unroll
                for (int h = 0; h < 4; h++) {
                    el4[h] += __shfl_xor_sync(0xFFFFFFFFu, el4[h], 1);
                    el4[h] += __shfl_xor_sync(0xFFFFFFFFu, el4[h], 2);
                    er4[h] += __shfl_xor_sync(0xFFFFFFFFu, er4[h], 1);
                    er4[h] += __shfl_xor_sync(0xFFFFFFFFu, er4[h], 2);
                }
                int n = n0 + rowg;
                if (n < NN) {
                    if (c4 == 0)
                        ((float4*)g_el)[(size_t)r * NN + n] = make_float4(el4[0], el4[1], el4[2], el4[3]);
                    else if (c4 == 1)
                        ((float4*)g_er)[(size_t)r * NN + n] = make_float4(er4[0], er4[1], er4[2], er4[3]);
                }
            }
        __syncthreads();

        {
            int n = n0 + tid;
            if (n < NN) {
                uint4* dst4 = (uint4*)(g_feat + ((size_t)r * NN + n) * 64);
#pragma unroll
                for (int c = 0; c < 8; c++) {
                    uint32_t off = SWZ((uint32_t)(tid * 128 + c * 16));
                    dst4[c] = *(const uint4*)((const char*)s_st + off);
                }
            }
        }
    }
}

// ================= CSR scan =================
__global__ void __launch_bounds__(256) k_scan_block() {
    __shared__ int ssum[256];
    int b = blockIdx.x, t = threadIdx.x;
    int base = b * 1024 + t * 4;
    int v[4], s = 0;
#pragma unroll
    for (int q = 0; q < 4; q++) {
        int idx = base + q;
        v[q] = (idx < NN) ? g_cnt[idx] : 0;
        s += v[q];
    }
    ssum[t] = s;
    __syncthreads();
#pragma unroll
    for (int off = 1; off < 256; off <<= 1) {
        int add = (t >= off) ? ssum[t - off] : 0;
        __syncthreads();
        ssum[t] += add;
        __syncthreads();
    }
    int excl = ssum[t] - s;
#pragma unroll
    for (int q = 0; q < 4; q++) {
        int idx = base + q;
        if (idx < NN) g_off[idx] = excl;
        excl += v[q];
    }
    if (t == 255) g_bsum[b] = ssum[255];
}
// addoff with inline prefix over block sums (kills k_scan_tops)
__global__ void __launch_bounds__(256) k_addoff() {
    __shared__ int s_add;
    int b = blockIdx.x, t = threadIdx.x;
    if (t < 32) {
        int v = 0;
        for (int j = t; j < b; j += 32) v += g_bsum[j];
#pragma unroll
        for (int o = 16; o; o >>= 1) v += __shfl_xor_sync(0xFFFFFFFFu, v, o);
        if (t == 0) s_add = v;
    }
    __syncthreads();
    int add = s_add;
    if (b == NBLK - 1 && t == 0) g_off[NN] = add + g_bsum[NBLK - 1];
    int base = b * 1024 + t * 4;
#pragma unroll
    for (int q = 0; q < 4; q++) {
        int idx = base + q;
        if (idx < NN) {
            int o = g_off[idx] + add;
            g_off[idx]  = o;
            g_wcur[idx] = o;
        }
    }
}
// scatter + fused exp (ev stored fp16)
__global__ void k_scatter(const int* __restrict__ src, const int* __restrict__ dst,
                          const int* __restrict__ erel) {
    int e = blockIdx.x * blockDim.x + threadIdx.x;
    if (e >= NE) return;
    int d = dst[e], s = src[e], r = erel[e];
    int idx = r * NN + s;
    float4 el = ((const float4*)g_el)[idx];
    float4 er = ((const float4*)g_er)[(size_t)r * NN + d];
    float sv[4] = {el.x + er.x, el.y + er.y, el.z + er.z, el.w + er.w};
    float ev[4];
#pragma unroll
    for (int h = 0; h < 4; h++) {
        float lv = sv[h] > 0.f ? sv[h] : 0.2f * sv[h];
        ev[h] = __expf(lv);
    }
    int pos = atomicAdd(&g_wcur[d], 1);
    g_epk[pos] = idx;
    uint2 pk = make_uint2(h2_to_u32(__floats2half2_rn(ev[0], ev[1])),
                          h2_to_u32(__floats2half2_rn(ev[2], ev[3])));
    *(uint2*)(g_ecsr + (size_t)pos * 4) = pk;
}

// ================= K2: pull aggregation (unroll x4, fp16 ev) ================
__global__ void __launch_bounds__(256) k_agg2(float* __restrict__ out,
                                              const float* __restrict__ bias) {
    int wid_in_blk = threadIdx.x >> 5;
    int lane = threadIdx.x & 31;
    int d = blockIdx.x * 8 + wid_in_blk;
    if (d >= NN) return;
    const int h = lane >> 3;
    const int hw = (h >> 1) * 4;     // byte offset of the half2 holding head h
    const int hs = h & 1;

    int beg = g_off[d];
    int end = g_off[d + 1];

    float accx = 0.f, accy = 0.f, dn = 0.f;

    int i = beg;
    for (; i + 4 <= end; i += 4) {
        int idx0 = g_epk[i], idx1 = g_epk[i + 1], idx2 = g_epk[i + 2], idx3 = g_epk[i + 3];
        unsigned u0 = *(const unsigned*)((const char*)(g_ecsr + (size_t)(i) * 4) + hw);
        unsigned u1 = *(const unsigned*)((const char*)(g_ecsr + (size_t)(i + 1) * 4) + hw);
        unsigned u2 = *(const unsigned*)((const char*)(g_ecsr + (size_t)(i + 2) * 4) + hw);
        unsigned u3 = *(const unsigned*)((const char*)(g_ecsr + (size_t)(i + 3) * 4) + hw);
        unsigned f0 = *(const unsigned*)(g_feat + (size_t)idx0 * 64 + 2 * lane);
        unsigned f1 = *(const unsigned*)(g_feat + (size_t)idx1 * 64 + 2 * lane);
        unsigned f2 = *(const unsigned*)(g_feat + (size_t)idx2 * 64 + 2 * lane);
        unsigned f3 = *(const unsigned*)(g_feat + (size_t)idx3 * 64 + 2 * lane);
        float2 e0 = __half22float2(u32_to_h2(u0));
        float2 e1 = __half22float2(u32_to_h2(u1));
        float2 e2 = __half22float2(u32_to_h2(u2));
        float2 e3 = __half22float2(u32_to_h2(u3));
        float ev0 = hs ? e0.y : e0.x;
        float ev1 = hs ? e1.y : e1.x;
        float ev2 = hs ? e2.y : e2.x;
        float ev3 = hs ? e3.y : e3.x;
        float2 p0 = __half22float2(u32_to_h2(f0));
        float2 p1 = __half22float2(u32_to_h2(f1));
        float2 p2 = __half22float2(u32_to_h2(f2));
        float2 p3 = __half22float2(u32_to_h2(f3));
        dn += (ev0 + ev1) + (ev2 + ev3);
        accx += p0.x * ev0 + p1.x * ev1 + p2.x * ev2 + p3.x * ev3;
        accy += p0.y * ev0 + p1.y * ev1 + p2.y * ev2 + p3.y * ev3;
    }
    for (; i < end; i++) {
        int idx0 = g_epk[i];
        unsigned u0 = *(const unsigned*)((const char*)(g_ecsr + (size_t)i * 4) + hw);
        unsigned f0 = *(const unsigned*)(g_feat + (size_t)idx0 * 64 + 2 * lane);
        float2 e0 = __half22float2(u32_to_h2(u0));
        float ev0 = hs ? e0.y : e0.x;
        float2 p0 = __half22float2(u32_to_h2(f0));
        dn += ev0;
        accx += p0.x * ev0;
        accy += p0.y * ev0;
    }

    float w;
    asm("rcp.approx.f32 %0, %1;" : "=f"(w) : "f"(fmaxf(dn, 1e-16f)));
    float2 o;
    o.x = accx * w + bias[2 * lane];
    o.y = accy * w + bias[2 * lane + 1];
    *(float2*)(out + (size_t)d * 64 + 2 * lane) = o;

    if (lane == 0) g_cnt[d] = 0;   // restore zero-invariant for next call
}

// ---------------- launch ----------------
extern "C" void kernel_launch(void* const* d_in, const int* in_sizes, int n_in,
                              void* d_out, int out_size) {
    const float* x    = (const float*)d_in[0];
    const int*   srci = (const int*)d_in[1];
    const int*   dsti = (const int*)d_in[2];
    const int*   erel = (const int*)d_in[3];
    const float* W    = (const float*)d_in[4];
    const float* al   = (const float*)d_in[5];
    const float* ar   = (const float*)d_in[6];
    const float* bias = (const float*)d_in[7];
    float* out = (float*)d_out;
    (void)in_sizes; (void)n_in; (void)out_size;

    k_feat_hist<<<FUSED_GRID, 128>>>(x, W, al, ar, dsti);
    k_scan_block<<<NBLK, 256>>>();
    k_addoff<<<NBLK, 256>>>();
    k_scatter<<<(NE + 255) / 256, 256>>>(srci, dsti, erel);
    k_agg2<<<(NN + 7) / 8, 256>>>(out, bias);
}

// round 15
// speedup vs baseline: 1.2748x; 1.0861x over previous
#include <cuda_runtime.h>
#include <cuda_fp16.h>
#include <cstdint>

#define NN   100000
#define NE   1000000
#define NR   8
#define NH   4
#define FIN  64
#define FOUT 64
#define DH   16
#define NBLK 98              // ceil(NN / 1024)

#define FEAT_BLOCKS 782      // ceil(NN/128)
#define HIST_BLOCKS 391      // every 3rd block of the fused grid
#define FUSED_GRID  (FEAT_BLOCKS + HIST_BLOCKS)   // 1173
#define HIST_EPB    2560     // edges per hist block (391*2560 >= 1e6)

// ---------------- scratch (device globals; allocation-free) ----------------
__device__ __align__(16) __half g_feat[(size_t)NR * NN * FOUT];  // 102.4 MB
__device__ __align__(16) float  g_el[(size_t)NR * NN * NH];      // 12.8 MB
__device__ __align__(16) float  g_er[(size_t)NR * NN * NH];      // 12.8 MB
__device__ int   g_cnt[NN];          // zero at entry (static init + agg2 restore)
__device__ int   g_off[NN + 1];
__device__ int   g_wcur[NN];
__device__ int   g_bsum[NBLK];
__device__ int   g_epk[NE];                                      // 4 MB  (idx = r*NN+s)
__device__ __align__(16) __half g_ecsr[(size_t)NE * NH];         // 8 MB (ev fp16, CSR order)

__device__ __forceinline__ unsigned h2_to_u32(__half2 h) {
    union { __half2 h; unsigned u; } c; c.h = h; return c.u;
}
__device__ __forceinline__ __half2 u32_to_h2(unsigned u) {
    union { unsigned u; __half2 h; } c; c.u = u; return c.h;
}
__device__ __forceinline__ uint32_t smem_u32(const void* p) {
    uint32_t a;
    asm("{ .reg .u64 t; cvta.to.shared.u64 t, %1; cvt.u32.u64 %0, t; }" : "=r"(a) : "l"(p));
    return a;
}
#define SWZ(off) ((off) ^ (((off) >> 3) & 0x70))

#define LDM_X4(r0, r1, r2, r3, a) \
    asm volatile("ldmatrix.sync.aligned.m8n8.x4.shared.b16 {%0,%1,%2,%3}, [%4];" \
                 : "=r"(r0), "=r"(r1), "=r"(r2), "=r"(r3) : "r"(a))

#define MMA(d, a, b0, b1) \
    asm volatile("mma.sync.aligned.m16n8k16.row.col.f32.f16.f16.f32 " \
                 "{%0,%1,%2,%3},{%4,%5,%6,%7},{%8,%9},{%0,%1,%2,%3};" \
                 : "+f"((d)[0]), "+f"((d)[1]), "+f"((d)[2]), "+f"((d)[3]) \
                 : "r"((a)[0]), "r"((a)[1]), "r"((a)[2]), "r"((a)[3]), "r"(b0), "r"(b1))

// ================= K1: fused feat-GEMM (mma.sync, 2-term) + dst histogram ===
// grid = FUSED_GRID; bid%3==2 -> histogram block, else feat block.
// D = xh*wh + xh*wl  (x single fp16, W split hi/lo)
__global__ void __launch_bounds__(128) k_feat_hist(const float* __restrict__ x,
                                                   const float* __restrict__ W,
                                                   const float* __restrict__ al,
                                                   const float* __restrict__ ar,
                                                   const int* __restrict__ dst) {
    __shared__ __align__(16) __half s_xh[128 * 64];  // 16 KB
    __shared__ __align__(16) __half s_wh[64 * 64];   //  8 KB
    __shared__ __align__(16) __half s_wl[64 * 64];   //  8 KB
    __shared__ __align__(16) __half s_st[128 * 64];  // 16 KB staging

    const int bid = blockIdx.x;
    const int tid = threadIdx.x;

    if (bid % 3 == 2) {
        // ---- histogram role ----
        int hb = bid / 3;
        int e0 = hb * HIST_EPB + tid;
        int eEnd = min((hb + 1) * HIST_EPB, NE);
#pragma unroll 4
        for (int e = e0; e < eEnd; e += 128)
            atomicAdd(&g_cnt[dst[e]], 1);
        return;
    }
    const int fb = bid - bid / 3;        // 0..FEAT_BLOCKS-1
    const int n0 = fb * 128;
    const int wid  = tid >> 5;
    const int lane = tid & 31;

    const uint32_t xh_b = smem_u32(s_xh);
    const uint32_t wh_b = smem_u32(s_wh);
    const uint32_t wl_b = smem_u32(s_wl);

    // ---- load x row ONCE (fp16, SW128 swizzled rows of 128B) ----
    {
        int gn = n0 + tid;
        const float4* xr = (const float4*)x + (size_t)gn * 16;
#pragma unroll
        for (int c = 0; c < 8; c++) {
            float4 v0, v1;
            if (gn < NN) { v0 = xr[2 * c]; v1 = xr[2 * c + 1]; }
            else { v0 = make_float4(0.f, 0.f, 0.f, 0.f); v1 = v0; }
            unsigned ph[4];
            ph[0] = h2_to_u32(__floats2half2_rn(v0.x, v0.y));
            ph[1] = h2_to_u32(__floats2half2_rn(v0.z, v0.w));
            ph[2] = h2_to_u32(__floats2half2_rn(v1.x, v1.y));
            ph[3] = h2_to_u32(__floats2half2_rn(v1.z, v1.w));
            uint32_t off = SWZ((uint32_t)(tid * 128 + c * 16));
            *(uint4*)((char*)s_xh + off) = make_uint4(ph[0], ph[1], ph[2], ph[3]);
        }
    }

    const int m0       = wid * 32;
    const int a_row_in = lane & 7;
    const int a_msel   = lane >> 3;
    const int b_f_in   = ((lane >> 4) << 3) + (lane & 7);
    const int b_kadd   = ((lane >> 3) & 1) * 8;
    const int q4 = lane >> 2;
    const int c4 = lane & 3;

    for (int r = 0; r < NR; r++) {
        __syncthreads();

        // ---- load W[r] as [f][i] rows (128B), split hi/lo ----
        for (int e = tid; e < 64 * 64; e += 128) {
            int f = e >> 6, i = e & 63;
            float v = W[(((size_t)(r * NH + (f >> 4)) * FIN + i) * DH) + (f & 15)];
            __half h = __float2half_rn(v);
            __half l = __float2half_rn(v - __half2float(h));
            uint32_t off = SWZ((uint32_t)(f * 128 + i * 2));
            *(__half*)((char*)s_wh + off) = h;
            *(__half*)((char*)s_wl + off) = l;
        }
        __syncthreads();

        float acc[2][8][4];
#pragma unroll
        for (int m = 0; m < 2; m++)
#pragma unroll
            for (int nt = 0; nt < 8; nt++)
#pragma unroll
                for (int q = 0; q < 4; q++) acc[m][nt][q] = 0.f;

#pragma unroll
        for (int ks = 0; ks < 4; ks++) {
            const int k0 = ks * 16;
            uint32_t ah[2][4];
#pragma unroll
            for (int m = 0; m < 2; m++) {
                int row = m0 + m * 16 + (a_msel & 1) * 8 + a_row_in;
                int kk  = k0 + (a_msel >> 1) * 8;
                uint32_t off = SWZ((uint32_t)(row * 128 + kk * 2));
                LDM_X4(ah[m][0], ah[m][1], ah[m][2], ah[m][3], xh_b + off);
            }
            uint32_t bh[4][4], bl[4][4];
#pragma unroll
            for (int p = 0; p < 4; p++) {
                int f  = p * 16 + b_f_in;
                int kk = k0 + b_kadd;
                uint32_t off = SWZ((uint32_t)(f * 128 + kk * 2));
                LDM_X4(bh[p][0], bh[p][1], bh[p][2], bh[p][3], wh_b + off);
                LDM_X4(bl[p][0], bl[p][1], bl[p][2], bl[p][3], wl_b + off);
            }
#pragma unroll
            for (int m = 0; m < 2; m++)
#pragma unroll
                for (int p = 0; p < 4; p++) {
                    MMA(acc[m][2 * p],     ah[m], bh[p][0], bh[p][1]);
                    MMA(acc[m][2 * p + 1], ah[m], bh[p][2], bh[p][3]);
                    MMA(acc[m][2 * p],     ah[m], bl[p][0], bl[p][1]);
                    MMA(acc[m][2 * p + 1], ah[m], bl[p][2], bl[p][3]);
                }
        }

        // ---- stage feat (fp16) into s_st; compute el/er ----
#pragma unroll
        for (int m = 0; m < 2; m++)
#pragma unroll
            for (int rh = 0; rh < 2; rh++) {
                int rowg = m0 + m * 16 + rh * 8 + q4;
#pragma unroll
                for (int nt = 0; nt < 8; nt++) {
                    __half2 hv = __floats2half2_rn(acc[m][nt][rh * 2], acc[m][nt][rh * 2 + 1]);
                    uint32_t off = SWZ((uint32_t)(rowg * 128 + (nt * 8 + c4 * 2) * 2));
                    *(unsigned*)((char*)s_st + off) = h2_to_u32(hv);
                }
                float el4[4] = {0.f, 0.f, 0.f, 0.f}, er4[4] = {0.f, 0.f, 0.f, 0.f};
#pragma unroll
                for (int nt = 0; nt < 8; nt++) {
                    int col = nt * 8 + c4 * 2;
                    int h = nt >> 1;
                    float v0 = acc[m][nt][rh * 2], v1 = acc[m][nt][rh * 2 + 1];
                    el4[h] += v0 * al[r * 64 + col] + v1 * al[r * 64 + col + 1];
                    er4[h] += v0 * ar[r * 64 + col] + v1 * ar[r * 64 + col + 1];
                }
#pragma unroll
                for (int h = 0; h < 4; h++) {
                    el4[h] += __shfl_xor_sync(0xFFFFFFFFu, el4[h], 1);
                    el4[h] += __shfl_xor_sync(0xFFFFFFFFu, el4[h], 2);
                    er4[h] += __shfl_xor_sync(0xFFFFFFFFu, er4[h], 1);
                    er4[h] += __shfl_xor_sync(0xFFFFFFFFu, er4[h], 2);
                }
                int n = n0 + rowg;
                if (n < NN) {
                    if (c4 == 0)
                        ((float4*)g_el)[(size_t)r * NN + n] = make_float4(el4[0], el4[1], el4[2], el4[3]);
                    else if (c4 == 1)
                        ((float4*)g_er)[(size_t)r * NN + n] = make_float4(er4[0], er4[1], er4[2], er4[3]);
                }
            }
        __syncthreads();

        {
            int n = n0 + tid;
            if (n < NN) {
                uint4* dst4 = (uint4*)(g_feat + ((size_t)r * NN + n) * 64);
#pragma unroll
                for (int c = 0; c < 8; c++) {
                    uint32_t off = SWZ((uint32_t)(tid * 128 + c * 16));
                    dst4[c] = *(const uint4*)((const char*)s_st + off);
                }
            }
        }
    }
}

// ================= CSR scan =================
__global__ void __launch_bounds__(256) k_scan_block() {
    __shared__ int ssum[256];
    int b = blockIdx.x, t = threadIdx.x;
    int base = b * 1024 + t * 4;
    int v[4], s = 0;
#pragma unroll
    for (int q = 0; q < 4; q++) {
        int idx = base + q;
        v[q] = (idx < NN) ? g_cnt[idx] : 0;
        s += v[q];
    }
    ssum[t] = s;
    __syncthreads();
#pragma unroll
    for (int off = 1; off < 256; off <<= 1) {
        int add = (t >= off) ? ssum[t - off] : 0;
        __syncthreads();
        ssum[t] += add;
        __syncthreads();
    }
    int excl = ssum[t] - s;
#pragma unroll
    for (int q = 0; q < 4; q++) {
        int idx = base + q;
        if (idx < NN) g_off[idx] = excl;
        excl += v[q];
    }
    if (t == 255) g_bsum[b] = ssum[255];
}
__global__ void __launch_bounds__(256) k_addoff() {
    __shared__ int s_add;
    int b = blockIdx.x, t = threadIdx.x;
    if (t < 32) {
        int v = 0;
        for (int j = t; j < b; j += 32) v += g_bsum[j];
#pragma unroll
        for (int o = 16; o; o >>= 1) v += __shfl_xor_sync(0xFFFFFFFFu, v, o);
        if (t == 0) s_add = v;
    }
    __syncthreads();
    int add = s_add;
    if (b == NBLK - 1 && t == 0) g_off[NN] = add + g_bsum[NBLK - 1];
    int base = b * 1024 + t * 4;
#pragma unroll
    for (int q = 0; q < 4; q++) {
        int idx = base + q;
        if (idx < NN) {
            int o = g_off[idx] + add;
            g_off[idx]  = o;
            g_wcur[idx] = o;
        }
    }
}
// scatter + fused exp (ev stored fp16)
__global__ void k_scatter(const int* __restrict__ src, const int* __restrict__ dst,
                          const int* __restrict__ erel) {
    int e = blockIdx.x * blockDim.x + threadIdx.x;
    if (e >= NE) return;
    int d = dst[e], s = src[e], r = erel[e];
    int idx = r * NN + s;
    float4 el = ((const float4*)g_el)[idx];
    float4 er = ((const float4*)g_er)[(size_t)r * NN + d];
    float sv[4] = {el.x + er.x, el.y + er.y, el.z + er.z, el.w + er.w};
    float ev[4];
#pragma unroll
    for (int h = 0; h < 4; h++) {
        float lv = sv[h] > 0.f ? sv[h] : 0.2f * sv[h];
        ev[h] = __expf(lv);
    }
    int pos = atomicAdd(&g_wcur[d], 1);
    g_epk[pos] = idx;
    uint2 pk = make_uint2(h2_to_u32(__floats2half2_rn(ev[0], ev[1])),
                          h2_to_u32(__floats2half2_rn(ev[2], ev[3])));
    *(uint2*)(g_ecsr + (size_t)pos * 4) = pk;
}

// ================= K2: pull aggregation (unroll x4, fp16 ev) ================
__global__ void __launch_bounds__(256) k_agg2(float* __restrict__ out,
                                              const float* __restrict__ bias) {
    int wid_in_blk = threadIdx.x >> 5;
    int lane = threadIdx.x & 31;
    int d = blockIdx.x * 8 + wid_in_blk;
    if (d >= NN) return;
    const int h = lane >> 3;
    const int hw = (h >> 1) * 4;
    const int hs = h & 1;

    int beg = g_off[d];
    int end = g_off[d + 1];

    float accx = 0.f, accy = 0.f, dn = 0.f;

    int i = beg;
    for (; i + 4 <= end; i += 4) {
        int idx0 = g_epk[i], idx1 = g_epk[i + 1], idx2 = g_epk[i + 2], idx3 = g_epk[i + 3];
        unsigned u0 = *(const unsigned*)((const char*)(g_ecsr + (size_t)(i) * 4) + hw);
        unsigned u1 = *(const unsigned*)((const char*)(g_ecsr + (size_t)(i + 1) * 4) + hw);
        unsigned u2 = *(const unsigned*)((const char*)(g_ecsr + (size_t)(i + 2) * 4) + hw);
        unsigned u3 = *(const unsigned*)((const char*)(g_ecsr + (size_t)(i + 3) * 4) + hw);
        unsigned f0 = *(const unsigned*)(g_feat + (size_t)idx0 * 64 + 2 * lane);
        unsigned f1 = *(const unsigned*)(g_feat + (size_t)idx1 * 64 + 2 * lane);
        unsigned f2 = *(const unsigned*)(g_feat + (size_t)idx2 * 64 + 2 * lane);
        unsigned f3 = *(const unsigned*)(g_feat + (size_t)idx3 * 64 + 2 * lane);
        float2 e0 = __half22float2(u32_to_h2(u0));
        float2 e1 = __half22float2(u32_to_h2(u1));
        float2 e2 = __half22float2(u32_to_h2(u2));
        float2 e3 = __half22float2(u32_to_h2(u3));
        float ev0 = hs ? e0.y : e0.x;
        float ev1 = hs ? e1.y : e1.x;
        float ev2 = hs ? e2.y : e2.x;
        float ev3 = hs ? e3.y : e3.x;
        float2 p0 = __half22float2(u32_to_h2(f0));
        float2 p1 = __half22float2(u32_to_h2(f1));
        float2 p2 = __half22float2(u32_to_h2(f2));
        float2 p3 = __half22float2(u32_to_h2(f3));
        dn += (ev0 + ev1) + (ev2 + ev3);
        accx += p0.x * ev0 + p1.x * ev1 + p2.x * ev2 + p3.x * ev3;
        accy += p0.y * ev0 + p1.y * ev1 + p2.y * ev2 + p3.y * ev3;
    }
    for (; i < end; i++) {
        int idx0 = g_epk[i];
        unsigned u0 = *(const unsigned*)((const char*)(g_ecsr + (size_t)i * 4) + hw);
        unsigned f0 = *(const unsigned*)(g_feat + (size_t)idx0 * 64 + 2 * lane);
        float2 e0 = __half22float2(u32_to_h2(u0));
        float ev0 = hs ? e0.y : e0.x;
        float2 p0 = __half22float2(u32_to_h2(f0));
        dn += ev0;
        accx += p0.x * ev0;
        accy += p0.y * ev0;
    }

    float w;
    asm("rcp.approx.f32 %0, %1;" : "=f"(w) : "f"(fmaxf(dn, 1e-16f)));
    float2 o;
    o.x = accx * w + bias[2 * lane];
    o.y = accy * w + bias[2 * lane + 1];
    *(float2*)(out + (size_t)d * 64 + 2 * lane) = o;

    if (lane == 0) g_cnt[d] = 0;   // restore zero-invariant for next call
}

// ---------------- launch ----------------
extern "C" void kernel_launch(void* const* d_in, const int* in_sizes, int n_in,
                              void* d_out, int out_size) {
    const float* x    = (const float*)d_in[0];
    const int*   srci = (const int*)d_in[1];
    const int*   dsti = (const int*)d_in[2];
    const int*   erel = (const int*)d_in[3];
    const float* W    = (const float*)d_in[4];
    const float* al   = (const float*)d_in[5];
    const float* ar   = (const float*)d_in[6];
    const float* bias = (const float*)d_in[7];
    float* out = (float*)d_out;
    (void)in_sizes; (void)n_in; (void)out_size;

    k_feat_hist<<<FUSED_GRID, 128>>>(x, W, al, ar, dsti);
    k_scan_block<<<NBLK, 256>>>();
    k_addoff<<<NBLK, 256>>>();
    k_scatter<<<(NE + 255) / 256, 256>>>(srci, dsti, erel);
    k_agg2<<<(NN + 7) / 8, 256>>>(out, bias);
}